// round 1
// baseline (speedup 1.0000x reference)
#include <cuda_runtime.h>
#include <math.h>

#define N_NODES 65536
#define B_G     128
#define N_PG    512
#define N_E     1048576
#define K_SEL   256

// ---------------- scratch (static device allocations) ----------------
__device__ int   g_deg[N_NODES];
__device__ int   g_off[N_NODES];
__device__ int   g_cur[N_NODES];
__device__ float g_dis[N_NODES];
__device__ int   g_csr[N_E];
__device__ float g_xw[(size_t)N_NODES * 128];
__device__ float g_h[(size_t)N_NODES * 384];
__device__ float g_spre[N_NODES];
__device__ float g_score[N_NODES];
__device__ float g_read[B_G * 768];
__device__ float g_z1[B_G * 256];
__device__ float g_z2[B_G * 128];

// ---------------- graph preprocessing ----------------
__global__ void k_zero_deg() {
    int i = blockIdx.x * 256 + threadIdx.x;
    if (i < N_NODES) g_deg[i] = 0;
}

__global__ void k_deg(const int* __restrict__ dst) {
    int e = blockIdx.x * 256 + threadIdx.x;
    if (e < N_E) atomicAdd(&g_deg[dst[e]], 1);
}

// one block (512 threads) per graph: dis = rsqrt(deg+1), exclusive scan -> CSR offsets
__global__ void k_scan() {
    int g = blockIdx.x, t = threadIdx.x;
    int n = g * N_PG + t;
    __shared__ int s[N_PG];
    int d = g_deg[n];
    s[t] = d;
    __syncthreads();
    for (int off = 1; off < N_PG; off <<= 1) {
        int v = (t >= off) ? s[t - off] : 0;
        __syncthreads();
        s[t] += v;
        __syncthreads();
    }
    int excl = s[t] - d;
    int o = g * (N_PG * 16) + excl;   // 8192 edges per graph
    g_off[n] = o;
    g_cur[n] = o;
    g_dis[n] = rsqrtf((float)(d + 1));
}

__global__ void k_fill(const int* __restrict__ src, const int* __restrict__ dst) {
    int e = blockIdx.x * 256 + threadIdx.x;
    if (e < N_E) {
        int p = atomicAdd(&g_cur[dst[e]], 1);
        g_csr[p] = src[e];
    }
}

// ---------------- generic SGEMM: C = A(MxK) * B(KxN) [+bias][+relu] ----------------
// 64x64 tile, BK=16, 256 threads, 4x4 per-thread microtile.
template <int MODE>  // 0: plain store, 1: bias + relu
__global__ void k_sgemm(const float* __restrict__ A, int lda,
                        const float* __restrict__ B, int ldb,
                        const float* __restrict__ bias,
                        float* __restrict__ C, int ldc, int Kdim) {
    __shared__ float As[16][68];
    __shared__ float Bs[16][68];

    int tid = threadIdx.x;
    int tx = tid & 15, ty = tid >> 4;
    int arow = tid >> 2, acol = (tid & 3) * 4;
    int brow = tid >> 4, bcol = (tid & 15) * 4;

    int row0 = blockIdx.y * 64;
    int col0 = blockIdx.x * 64;

    const float* Aptr = A + (size_t)(row0 + arow) * lda + acol;
    const float* Bptr = B + (size_t)brow * ldb + col0 + bcol;

    float acc[4][4];
#pragma unroll
    for (int i = 0; i < 4; i++)
#pragma unroll
        for (int j = 0; j < 4; j++) acc[i][j] = 0.f;

    for (int k0 = 0; k0 < Kdim; k0 += 16) {
        float4 a = *(const float4*)(Aptr + k0);
        float4 b = *(const float4*)(Bptr + (size_t)k0 * ldb);
        As[acol + 0][arow] = a.x;
        As[acol + 1][arow] = a.y;
        As[acol + 2][arow] = a.z;
        As[acol + 3][arow] = a.w;
        *(float4*)&Bs[brow][bcol] = b;
        __syncthreads();
#pragma unroll
        for (int k = 0; k < 16; k++) {
            float ar[4], br[4];
            *(float4*)ar = *(const float4*)&As[k][ty * 4];
            *(float4*)br = *(const float4*)&Bs[k][tx * 4];
#pragma unroll
            for (int i = 0; i < 4; i++)
#pragma unroll
                for (int j = 0; j < 4; j++) acc[i][j] += ar[i] * br[j];
        }
        __syncthreads();
    }

#pragma unroll
    for (int i = 0; i < 4; i++) {
#pragma unroll
        for (int j = 0; j < 4; j++) {
            int col = col0 + tx * 4 + j;
            float v = acc[i][j];
            if (MODE == 1) v = fmaxf(v + bias[col], 0.f);
            C[(size_t)(row0 + ty * 4 + i) * ldc + col] = v;
        }
    }
}

// ---------------- GCN aggregate: out[n] = relu(dis^2*xw[n] + dis[n]*sum dis[s]*xw[s] + b) ----------------
// warp per node, lane covers 4 columns (128 cols total)
__global__ void k_aggregate(const float* __restrict__ bias, float* __restrict__ out) {
    int wid = (blockIdx.x * blockDim.x + threadIdx.x) >> 5;
    int lane = threadIdx.x & 31;
    if (wid >= N_NODES) return;
    int n = wid;
    float dn = g_dis[n];
    int st = g_off[n], en = st + g_deg[n];

    const float4* xw = (const float4*)g_xw;
    float4 v = xw[(size_t)n * 32 + lane];
    float sc = dn * dn;
    float4 acc = make_float4(sc * v.x, sc * v.y, sc * v.z, sc * v.w);

    for (int j = st; j < en; j++) {
        int s = g_csr[j];
        float w = dn * g_dis[s];
        float4 u = xw[(size_t)s * 32 + lane];
        acc.x += w * u.x;
        acc.y += w * u.y;
        acc.z += w * u.z;
        acc.w += w * u.w;
    }
    float4 bb = *(const float4*)(bias + lane * 4);
    float4 r = make_float4(fmaxf(acc.x + bb.x, 0.f), fmaxf(acc.y + bb.y, 0.f),
                           fmaxf(acc.z + bb.z, 0.f), fmaxf(acc.w + bb.w, 0.f));
    *(float4*)(out + (size_t)n * 384 + lane * 4) = r;
}

// ---------------- score GEMV: s_pre = h_cat @ Ws (384 -> 1), warp per node ----------------
__global__ void k_score_gemv(const float* __restrict__ Ws) {
    int wid = (blockIdx.x * blockDim.x + threadIdx.x) >> 5;
    int lane = threadIdx.x & 31;
    if (wid >= N_NODES) return;
    const float* h = g_h + (size_t)wid * 384;
    float acc = 0.f;
#pragma unroll
    for (int c = 0; c < 384; c += 32) acc += h[c + lane] * Ws[c + lane];
#pragma unroll
    for (int o = 16; o; o >>= 1) acc += __shfl_xor_sync(0xffffffffu, acc, o);
    if (lane == 0) g_spre[wid] = acc;
}

// scalar CSR aggregate for score
__global__ void k_score_agg(const float* __restrict__ bs) {
    int n = blockIdx.x * 256 + threadIdx.x;
    if (n >= N_NODES) return;
    float dn = g_dis[n];
    float acc = dn * dn * g_spre[n];
    int st = g_off[n], en = st + g_deg[n];
    for (int j = st; j < en; j++) {
        int s = g_csr[j];
        acc += dn * g_dis[s] * g_spre[s];
    }
    g_score[n] = acc + bs[0];
}

// ---------------- fused per-graph top-k (bitonic sort) + gated max/mean readout ----------------
__global__ void k_pool() {
    int g = blockIdx.x, t = threadIdx.x;  // 512 threads
    __shared__ unsigned long long key[N_PG];
    __shared__ int sel[K_SEL];
    __shared__ float gate[K_SEL];

    float sc = g_score[g * N_PG + t];
    unsigned u = __float_as_uint(sc);
    u = (u & 0x80000000u) ? ~u : (u ^ 0x80000000u);  // ascending-orderable
    u = ~u;                                           // descending
    key[t] = ((unsigned long long)u << 32) | (unsigned)t;
    __syncthreads();

    for (int k = 2; k <= N_PG; k <<= 1) {
        for (int j = k >> 1; j > 0; j >>= 1) {
            int ixj = t ^ j;
            if (ixj > t) {
                unsigned long long a = key[t], b = key[ixj];
                bool up = ((t & k) == 0);
                if ((a > b) == up) { key[t] = b; key[ixj] = a; }
            }
            __syncthreads();
        }
    }

    if (t < K_SEL) {
        int idx = (int)(key[t] & 0xffffffffu);
        sel[t] = idx;
        gate[t] = tanhf(g_score[g * N_PG + idx]);
    }
    __syncthreads();

    if (t < 384) {
        float vmax = __int_as_float(0xff800000);  // -inf
        float vsum = 0.f;
        const float* hb = g_h + (size_t)g * N_PG * 384;
        for (int i = 0; i < K_SEL; i++) {
            float v = hb[(size_t)sel[i] * 384 + t] * gate[i];
            vmax = fmaxf(vmax, v);
            vsum += v;
        }
        g_read[g * 768 + t] = vmax;
        g_read[g * 768 + 384 + t] = vsum * (1.0f / K_SEL);
    }
}

// ---------------- final layer + log_softmax: warp per graph ----------------
__global__ void k_final(const float* __restrict__ Wl3, const float* __restrict__ bl3,
                        float* __restrict__ out) {
    int r = blockIdx.x;
    int lane = threadIdx.x;  // 32 threads
    float4 zv = *(const float4*)(g_z2 + r * 128 + lane * 4);
    float logits[10];
#pragma unroll
    for (int o = 0; o < 10; o++) {
        int k = lane * 4;
        float p = zv.x * Wl3[(k + 0) * 10 + o] + zv.y * Wl3[(k + 1) * 10 + o] +
                  zv.z * Wl3[(k + 2) * 10 + o] + zv.w * Wl3[(k + 3) * 10 + o];
#pragma unroll
        for (int s = 16; s; s >>= 1) p += __shfl_xor_sync(0xffffffffu, p, s);
        logits[o] = p + bl3[o];
    }
    if (lane == 0) {
        float m = logits[0];
#pragma unroll
        for (int o = 1; o < 10; o++) m = fmaxf(m, logits[o]);
        float se = 0.f;
#pragma unroll
        for (int o = 0; o < 10; o++) se += expf(logits[o] - m);
        float lse = m + logf(se);
#pragma unroll
        for (int o = 0; o < 10; o++) out[r * 10 + o] = logits[o] - lse;
    }
}

// ---------------- launcher ----------------
extern "C" void kernel_launch(void* const* d_in, const int* in_sizes, int n_in,
                              void* d_out, int out_size) {
    const float* x   = (const float*)d_in[0];
    const int*   ei  = (const int*)d_in[1];
    const float* W1  = (const float*)d_in[2];
    const float* b1  = (const float*)d_in[3];
    const float* W2  = (const float*)d_in[4];
    const float* b2  = (const float*)d_in[5];
    const float* W3  = (const float*)d_in[6];
    const float* b3  = (const float*)d_in[7];
    const float* Ws  = (const float*)d_in[8];
    const float* bs  = (const float*)d_in[9];
    const float* Wl1 = (const float*)d_in[10];
    const float* bl1 = (const float*)d_in[11];
    const float* Wl2 = (const float*)d_in[12];
    const float* bl2 = (const float*)d_in[13];
    const float* Wl3 = (const float*)d_in[14];
    const float* bl3 = (const float*)d_in[15];

    const int* src = ei;
    const int* dst = ei + N_E;

    void* p;
    cudaGetSymbolAddress(&p, g_xw);   float* xw = (float*)p;
    cudaGetSymbolAddress(&p, g_h);    float* h  = (float*)p;
    cudaGetSymbolAddress(&p, g_read); float* rd = (float*)p;
    cudaGetSymbolAddress(&p, g_z1);   float* z1 = (float*)p;
    cudaGetSymbolAddress(&p, g_z2);   float* z2 = (float*)p;

    // graph preprocessing
    k_zero_deg<<<N_NODES / 256, 256>>>();
    k_deg<<<N_E / 256, 256>>>(dst);
    k_scan<<<B_G, N_PG>>>();
    k_fill<<<N_E / 256, 256>>>(src, dst);

    dim3 gBig(2, N_NODES / 64);  // N=128 cols, M=65536 rows
    int aggBlocks = (N_NODES * 32) / 256;

    // layer 1: xw = x @ W1 ; h1 = agg(xw) -> g_h[:, 0:128]
    k_sgemm<0><<<gBig, 256>>>(x, 128, W1, 128, nullptr, xw, 128, 128);
    k_aggregate<<<aggBlocks, 256>>>(b1, h + 0);
    // layer 2: xw = h1 @ W2 ; h2 -> g_h[:, 128:256]
    k_sgemm<0><<<gBig, 256>>>(h + 0, 384, W2, 128, nullptr, xw, 128, 128);
    k_aggregate<<<aggBlocks, 256>>>(b2, h + 128);
    // layer 3: xw = h2 @ W3 ; h3 -> g_h[:, 256:384]
    k_sgemm<0><<<gBig, 256>>>(h + 128, 384, W3, 128, nullptr, xw, 128, 128);
    k_aggregate<<<aggBlocks, 256>>>(b3, h + 256);

    // SAGPool score
    k_score_gemv<<<aggBlocks, 256>>>(Ws);
    k_score_agg<<<N_NODES / 256, 256>>>(bs);

    // top-k + gated readout
    k_pool<<<B_G, N_PG>>>();

    // MLP head
    k_sgemm<1><<<dim3(4, 2), 256>>>(rd, 768, Wl1, 256, bl1, z1, 256, 768);
    k_sgemm<1><<<dim3(2, 2), 256>>>(z1, 256, Wl2, 128, bl2, z2, 128, 256);
    k_final<<<B_G, 32>>>(Wl3, bl3, (float*)d_out);
}